// round 5
// baseline (speedup 1.0000x reference)
#include <cuda_runtime.h>
#include <cstdint>

// ----------------------------- problem constants -----------------------------
#define M_DIM 8192
#define N_DIM 4096
#define K_DIM 4096
#define FP8MAX 448.0f
#define EPSV 1e-12f

// ----------------------------- GEMM tiling ----------------------------------
#define BM 128
#define BN 128
#define BK 128                  // K bytes (fp8 elems) per stage (4 x k32 steps)
#define STAGES 3
#define KT (K_DIM / BK)         // 32 k-tiles

// per-stage smem: A[128][128B] + B[128][128B] = 32 KB
#define STG_BYTES 32768
#define B_OFF 16384
#define SMEM_BYTES (STAGES * STG_BYTES)   // 98304

// ----------------------------- scratch (static device mem) ------------------
__device__ __align__(256) uint8_t g_Xq[(size_t)M_DIM * K_DIM];
__device__ __align__(256) uint8_t g_Wq[(size_t)N_DIM * K_DIM];
__device__ __align__(16) float g_Xs[M_DIM];
__device__ __align__(16) float g_Ws[N_DIM];

// ----------------------------- PTX helpers ----------------------------------
__device__ __forceinline__ uint32_t smem_u32(const void* p) {
    uint32_t a;
    asm("{ .reg .u64 t; cvta.to.shared.u64 t, %1; cvt.u32.u64 %0, t; }"
        : "=r"(a) : "l"(p));
    return a;
}
__device__ __forceinline__ void cp16(uint32_t s, const void* g) {
    asm volatile("cp.async.cg.shared.global [%0], [%1], 16;" :: "r"(s), "l"(g));
}
__device__ __forceinline__ void cp_commit() {
    asm volatile("cp.async.commit_group;" ::: "memory");
}
template <int N>
__device__ __forceinline__ void cp_wait() {
    asm volatile("cp.async.wait_group %0;" :: "n"(N) : "memory");
}
__device__ __forceinline__ void ldsm4(uint32_t* r, uint32_t addr) {
    asm volatile("ldmatrix.sync.aligned.m8n8.x4.shared.b16 {%0,%1,%2,%3}, [%4];"
                 : "=r"(r[0]), "=r"(r[1]), "=r"(r[2]), "=r"(r[3]) : "r"(addr));
}
__device__ __forceinline__ void mma_fp8(float* d, const uint32_t* a,
                                        uint32_t b0, uint32_t b1) {
    asm volatile(
        "mma.sync.aligned.m16n8k32.row.col.f32.e4m3.e4m3.f32 "
        "{%0,%1,%2,%3}, {%4,%5,%6,%7}, {%8,%9}, {%0,%1,%2,%3};"
        : "+f"(d[0]), "+f"(d[1]), "+f"(d[2]), "+f"(d[3])
        : "r"(a[0]), "r"(a[1]), "r"(a[2]), "r"(a[3]), "r"(b0), "r"(b1));
}
// pack two f32 -> e4m3x2 (lo in low byte), RN + satfinite
__device__ __forceinline__ uint16_t cvt_e4m3x2(float lo, float hi) {
    uint16_t r;
    asm volatile("cvt.rn.satfinite.e4m3x2.f32 %0, %1, %2;" : "=h"(r) : "f"(hi), "f"(lo));
    return r;
}

// ----------------------------- weight quant ---------------------------------
__global__ void __launch_bounds__(256) wquant_kernel(const float* __restrict__ w) {
    const int row = blockIdx.x;
    const float4* wr = (const float4*)(w + (size_t)row * K_DIM);

    float4 v[4];
    float mx = 0.f;
#pragma unroll
    for (int i = 0; i < 4; i++) {
        v[i] = wr[threadIdx.x + i * 256];
        mx = fmaxf(mx, fmaxf(fmaxf(fabsf(v[i].x), fabsf(v[i].y)),
                             fmaxf(fabsf(v[i].z), fabsf(v[i].w))));
    }
    __shared__ float red[8];
    __shared__ float s_scale;
#pragma unroll
    for (int o = 16; o; o >>= 1) mx = fmaxf(mx, __shfl_xor_sync(0xffffffffu, mx, o));
    if ((threadIdx.x & 31) == 0) red[threadIdx.x >> 5] = mx;
    __syncthreads();
    if (threadIdx.x == 0) {
        float m = red[0];
#pragma unroll
        for (int j = 1; j < 8; j++) m = fmaxf(m, red[j]);
        float sc = __fdiv_rn(fmaxf(m, EPSV), FP8MAX);
        s_scale = sc;
        g_Ws[row] = sc;
    }
    __syncthreads();
    const float sc = s_scale;

    uint32_t* oq = (uint32_t*)(g_Wq + (size_t)row * K_DIM);
#pragma unroll
    for (int i = 0; i < 4; i++) {
        uint16_t lo = cvt_e4m3x2(__fdiv_rn(v[i].x, sc), __fdiv_rn(v[i].y, sc));
        uint16_t hi = cvt_e4m3x2(__fdiv_rn(v[i].z, sc), __fdiv_rn(v[i].w, sc));
        oq[threadIdx.x + i * 256] = (uint32_t)lo | ((uint32_t)hi << 16);
    }
}

// ----------------------------- activation quant -----------------------------
__global__ void __launch_bounds__(256) aquant_kernel(const float* __restrict__ x) {
    const int row = blockIdx.x;
    const float4* xr = (const float4*)(x + (size_t)row * K_DIM);

    float a0[4], a1[4], a2[4], a3[4];
    float mx = 0.f;
#pragma unroll
    for (int i = 0; i < 4; i++) {
        float4 v = xr[threadIdx.x + i * 256];
        float r0 = fmaxf(v.x, 0.f), r1 = fmaxf(v.y, 0.f);
        float r2 = fmaxf(v.z, 0.f), r3 = fmaxf(v.w, 0.f);
        a0[i] = r0 * r0; a1[i] = r1 * r1; a2[i] = r2 * r2; a3[i] = r3 * r3;
        mx = fmaxf(mx, fmaxf(fmaxf(a0[i], a1[i]), fmaxf(a2[i], a3[i])));
    }
    __shared__ float red[8];
    __shared__ float s_scale;
#pragma unroll
    for (int o = 16; o; o >>= 1) mx = fmaxf(mx, __shfl_xor_sync(0xffffffffu, mx, o));
    if ((threadIdx.x & 31) == 0) red[threadIdx.x >> 5] = mx;
    __syncthreads();
    if (threadIdx.x == 0) {
        float m = red[0];
#pragma unroll
        for (int j = 1; j < 8; j++) m = fmaxf(m, red[j]);
        float sc = __fdiv_rn(fmaxf(m, EPSV), FP8MAX);
        s_scale = sc;
        g_Xs[row] = sc;
    }
    __syncthreads();
    const float sc = s_scale;

    uint32_t* oq = (uint32_t*)(g_Xq + (size_t)row * K_DIM);
#pragma unroll
    for (int i = 0; i < 4; i++) {
        float b0 = a0[i], b1 = a1[i], b2 = a2[i], b3 = a3[i];
        int i1 = 0; float m1 = b0;
        if (b1 > m1) { m1 = b1; i1 = 1; }
        if (b2 > m1) { m1 = b2; i1 = 2; }
        if (b3 > m1) { m1 = b3; i1 = 3; }
        float c0 = (i1 == 0) ? -1.f : b0;
        float c1 = (i1 == 1) ? -1.f : b1;
        float c2 = (i1 == 2) ? -1.f : b2;
        float c3 = (i1 == 3) ? -1.f : b3;
        int i2 = 0; float m2 = c0;
        if (c1 > m2) { m2 = c1; i2 = 1; }
        if (c2 > m2) { m2 = c2; i2 = 2; }
        if (c3 > m2) { m2 = c3; i2 = 3; }

        float q0 = (i1 == 0 || i2 == 0) ? __fdiv_rn(b0, sc) : 0.f;
        float q1 = (i1 == 1 || i2 == 1) ? __fdiv_rn(b1, sc) : 0.f;
        float q2 = (i1 == 2 || i2 == 2) ? __fdiv_rn(b2, sc) : 0.f;
        float q3 = (i1 == 3 || i2 == 3) ? __fdiv_rn(b3, sc) : 0.f;

        uint16_t lo = cvt_e4m3x2(q0, q1);
        uint16_t hi = cvt_e4m3x2(q2, q3);
        oq[threadIdx.x + i * 256] = (uint32_t)lo | ((uint32_t)hi << 16);
    }
}

// ----------------------------- dense fp8 GEMM -------------------------------
// 128x128 CTA tile, 8 warps (2x4), warp tile 64x32. BK=128 per stage
// (4 x k32 steps), 3-stage cp.async ring, 2 CTAs/SM.
// 128B rows = two 64B halves; within each half, 16B chunk swizzle
// chunk' = chunk ^ ((row>>1)&3).  addr(c) = row*128 + (c>>2)*64 + ((c&3)^swz)*16.
__global__ void __launch_bounds__(256, 2) gemm_kernel(float* __restrict__ out) {
    extern __shared__ uint32_t sm[];
    const uint32_t sb = smem_u32(sm);
    const int tid = threadIdx.x;
    const int wid = tid >> 5;
    const int lane = tid & 31;
    const int gid = lane >> 2;
    const int t4 = lane & 3;
    const int wm = (wid >> 2) * 64;
    const int wn = (wid & 3) * 32;
    const int m0 = blockIdx.y * BM;
    const int n0 = blockIdx.x * BN;

    // ---- ldmatrix lane address components ----
    const int ar = lane & 15;
    const uint32_t hiA = (uint32_t)lane >> 4;          // chunk +0/+1 within k32
    const uint32_t swzA = ((uint32_t)ar >> 1) & 3;
    const uint32_t aArow = (uint32_t)(wm + ar) * 128;
    const uint32_t swzB = ((uint32_t)lane >> 1) & 3;
    const uint32_t aBrow = B_OFF + (uint32_t)(wn + lane) * 128;

    // ---- producer mapping: threads 0-127 -> A rows, 128-255 -> B rows ----
    const int prow = tid & 127;
    const uint8_t* gP = (tid < 128)
        ? g_Xq + (size_t)(m0 + prow) * K_DIM
        : g_Wq + (size_t)(n0 + prow) * K_DIM;
    const uint32_t swzP = ((uint32_t)prow >> 1) & 3;
    const uint32_t sProw = sb + ((tid < 128) ? 0u : (uint32_t)B_OFF) + (uint32_t)prow * 128;

    float acc[4][4][4];
#pragma unroll
    for (int i = 0; i < 4; i++)
#pragma unroll
        for (int j = 0; j < 4; j++)
#pragma unroll
            for (int c = 0; c < 4; c++) acc[i][j][c] = 0.f;

    // ---- prologue: fill STAGES-1 stages ----
#pragma unroll
    for (int s = 0; s < STAGES - 1; s++) {
        const uint32_t po = s * STG_BYTES;
        const uint8_t* src = gP + (size_t)s * BK;
#pragma unroll
        for (int c = 0; c < 8; c++)
            cp16(sProw + po + ((c >> 2) << 6) + ((((uint32_t)c & 3) ^ swzP) << 4),
                 src + c * 16);
        cp_commit();
    }

    // ---- main loop ----
#pragma unroll 1
    for (int kt = 0; kt < KT; kt++) {
        cp_wait<STAGES - 2>();
        __syncthreads();

        if (kt + STAGES - 1 < KT) {
            const uint32_t po = ((kt + STAGES - 1) % STAGES) * STG_BYTES;
            const uint8_t* src = gP + (size_t)(kt + STAGES - 1) * BK;
#pragma unroll
            for (int c = 0; c < 8; c++)
                cp16(sProw + po + ((c >> 2) << 6) + ((((uint32_t)c & 3) ^ swzP) << 4),
                     src + c * 16);
        }
        cp_commit();

        const uint32_t co = (kt % STAGES) * STG_BYTES;
#pragma unroll
        for (int j = 0; j < 4; j++) {     // four k32 steps per stage
            // A chunk index = 2j + hiA ; B chunks 2j, 2j+1
            const uint32_t cA = 2u * j + hiA;
            const uint32_t offA = ((cA >> 2) << 6) + (((cA & 3) ^ swzA) << 4);
            const uint32_t cB0 = 2u * j;
            const uint32_t offB0 = ((cB0 >> 2) << 6) + (((cB0 & 3) ^ swzB) << 4);
            const uint32_t cB1 = 2u * j + 1;
            const uint32_t offB1 = ((cB1 >> 2) << 6) + (((cB1 & 3) ^ swzB) << 4);

            uint32_t af[4][4], b0[4], b1[4];
#pragma unroll
            for (int mi = 0; mi < 4; mi++)
                ldsm4(af[mi], sb + co + aArow + (uint32_t)mi * 2048 + offA);
            ldsm4(b0, co + aBrow + offB0 + sb);
            ldsm4(b1, co + aBrow + offB1 + sb);

#pragma unroll
            for (int mi = 0; mi < 4; mi++)
#pragma unroll
                for (int ni = 0; ni < 4; ni++)
                    mma_fp8(acc[mi][ni], af[mi], b0[ni], b1[ni]);
        }
    }

    // ---- epilogue: rescale + store ----
#pragma unroll
    for (int mi = 0; mi < 4; mi++) {
        const int r0 = m0 + wm + mi * 16 + gid;
        const float xs0 = g_Xs[r0];
        const float xs1 = g_Xs[r0 + 8];
#pragma unroll
        for (int ni = 0; ni < 4; ni++) {
            const int c = n0 + wn + ni * 8 + t4 * 2;
            const float ws0 = g_Ws[c];
            const float ws1 = g_Ws[c + 1];
            float2 o0, o1;
            o0.x = acc[mi][ni][0] * xs0 * ws0;
            o0.y = acc[mi][ni][1] * xs0 * ws1;
            o1.x = acc[mi][ni][2] * xs1 * ws0;
            o1.y = acc[mi][ni][3] * xs1 * ws1;
            *(float2*)(out + (size_t)r0 * N_DIM + c) = o0;
            *(float2*)(out + (size_t)(r0 + 8) * N_DIM + c) = o1;
        }
    }
}

// ----------------------------- launch ---------------------------------------
extern "C" void kernel_launch(void* const* d_in, const int* in_sizes, int n_in,
                              void* d_out, int out_size) {
    const float* x = (const float*)d_in[0];   // [8192, 4096] f32
    const float* w = (const float*)d_in[1];   // [4096, 4096] f32
    float* out = (float*)d_out;               // [8192, 4096] f32
    (void)in_sizes; (void)n_in; (void)out_size;

    cudaFuncSetAttribute(gemm_kernel,
                         cudaFuncAttributeMaxDynamicSharedMemorySize, SMEM_BYTES);

    wquant_kernel<<<N_DIM, 256>>>(w);
    aquant_kernel<<<M_DIM, 256>>>(x);
    gemm_kernel<<<dim3(N_DIM / BN, M_DIM / BM), 256, SMEM_BYTES>>>(out);
}

// round 6
// speedup vs baseline: 1.2528x; 1.2528x over previous
#include <cuda_runtime.h>
#include <cstdint>

// ----------------------------- problem constants -----------------------------
#define M_DIM 8192
#define N_DIM 4096
#define K_DIM 4096
#define FP8MAX 448.0f
#define EPSV 1e-12f

// ----------------------------- GEMM tiling ----------------------------------
#define BM 128
#define BN 256
#define BK 64                   // K bytes (fp8 elems) per stage
#define STAGES 6
#define KT (K_DIM / BK)         // 64 k-tiles

// per-stage smem: A[128][64B] + B[256][64B] = 24 KB
#define STG_BYTES 24576
#define B_OFF 8192
#define SMEM_BYTES (STAGES * STG_BYTES)   // 147456

// ----------------------------- scratch (static device mem) ------------------
__device__ __align__(256) uint8_t g_Xq[(size_t)M_DIM * K_DIM];
__device__ __align__(256) uint8_t g_Wq[(size_t)N_DIM * K_DIM];
__device__ __align__(16) float g_Xs[M_DIM];
__device__ __align__(16) float g_Ws[N_DIM];

// ----------------------------- PTX helpers ----------------------------------
__device__ __forceinline__ uint32_t smem_u32(const void* p) {
    uint32_t a;
    asm("{ .reg .u64 t; cvta.to.shared.u64 t, %1; cvt.u32.u64 %0, t; }"
        : "=r"(a) : "l"(p));
    return a;
}
__device__ __forceinline__ void cp16(uint32_t s, const void* g) {
    asm volatile("cp.async.cg.shared.global [%0], [%1], 16;" :: "r"(s), "l"(g));
}
__device__ __forceinline__ void cp_commit() {
    asm volatile("cp.async.commit_group;" ::: "memory");
}
template <int N>
__device__ __forceinline__ void cp_wait() {
    asm volatile("cp.async.wait_group %0;" :: "n"(N) : "memory");
}
__device__ __forceinline__ void ldsm4(uint32_t* r, uint32_t addr) {
    asm volatile("ldmatrix.sync.aligned.m8n8.x4.shared.b16 {%0,%1,%2,%3}, [%4];"
                 : "=r"(r[0]), "=r"(r[1]), "=r"(r[2]), "=r"(r[3]) : "r"(addr));
}
__device__ __forceinline__ void mma_fp8(float* d, const uint32_t* a,
                                        uint32_t b0, uint32_t b1) {
    asm volatile(
        "mma.sync.aligned.m16n8k32.row.col.f32.e4m3.e4m3.f32 "
        "{%0,%1,%2,%3}, {%4,%5,%6,%7}, {%8,%9}, {%0,%1,%2,%3};"
        : "+f"(d[0]), "+f"(d[1]), "+f"(d[2]), "+f"(d[3])
        : "r"(a[0]), "r"(a[1]), "r"(a[2]), "r"(a[3]), "r"(b0), "r"(b1));
}
// pack two f32 -> e4m3x2 (lo in low byte), RN + satfinite
__device__ __forceinline__ uint16_t cvt_e4m3x2(float lo, float hi) {
    uint16_t r;
    asm volatile("cvt.rn.satfinite.e4m3x2.f32 %0, %1, %2;" : "=h"(r) : "f"(hi), "f"(lo));
    return r;
}

// ----------------------------- weight quant ---------------------------------
__global__ void __launch_bounds__(256) wquant_kernel(const float* __restrict__ w) {
    const int row = blockIdx.x;
    const float4* wr = (const float4*)(w + (size_t)row * K_DIM);

    float4 v[4];
    float mx = 0.f;
#pragma unroll
    for (int i = 0; i < 4; i++) {
        v[i] = wr[threadIdx.x + i * 256];
        mx = fmaxf(mx, fmaxf(fmaxf(fabsf(v[i].x), fabsf(v[i].y)),
                             fmaxf(fabsf(v[i].z), fabsf(v[i].w))));
    }
    __shared__ float red[8];
    __shared__ float s_scale;
#pragma unroll
    for (int o = 16; o; o >>= 1) mx = fmaxf(mx, __shfl_xor_sync(0xffffffffu, mx, o));
    if ((threadIdx.x & 31) == 0) red[threadIdx.x >> 5] = mx;
    __syncthreads();
    if (threadIdx.x == 0) {
        float m = red[0];
#pragma unroll
        for (int j = 1; j < 8; j++) m = fmaxf(m, red[j]);
        float sc = __fdiv_rn(fmaxf(m, EPSV), FP8MAX);
        s_scale = sc;
        g_Ws[row] = sc;
    }
    __syncthreads();
    const float sc = s_scale;

    uint32_t* oq = (uint32_t*)(g_Wq + (size_t)row * K_DIM);
#pragma unroll
    for (int i = 0; i < 4; i++) {
        uint16_t lo = cvt_e4m3x2(__fdiv_rn(v[i].x, sc), __fdiv_rn(v[i].y, sc));
        uint16_t hi = cvt_e4m3x2(__fdiv_rn(v[i].z, sc), __fdiv_rn(v[i].w, sc));
        oq[threadIdx.x + i * 256] = (uint32_t)lo | ((uint32_t)hi << 16);
    }
}

// ----------------------------- activation quant -----------------------------
__global__ void __launch_bounds__(256) aquant_kernel(const float* __restrict__ x) {
    const int row = blockIdx.x;
    const float4* xr = (const float4*)(x + (size_t)row * K_DIM);

    float a0[4], a1[4], a2[4], a3[4];
    float mx = 0.f;
#pragma unroll
    for (int i = 0; i < 4; i++) {
        float4 v = xr[threadIdx.x + i * 256];
        float r0 = fmaxf(v.x, 0.f), r1 = fmaxf(v.y, 0.f);
        float r2 = fmaxf(v.z, 0.f), r3 = fmaxf(v.w, 0.f);
        a0[i] = r0 * r0; a1[i] = r1 * r1; a2[i] = r2 * r2; a3[i] = r3 * r3;
        mx = fmaxf(mx, fmaxf(fmaxf(a0[i], a1[i]), fmaxf(a2[i], a3[i])));
    }
    __shared__ float red[8];
    __shared__ float s_scale;
#pragma unroll
    for (int o = 16; o; o >>= 1) mx = fmaxf(mx, __shfl_xor_sync(0xffffffffu, mx, o));
    if ((threadIdx.x & 31) == 0) red[threadIdx.x >> 5] = mx;
    __syncthreads();
    if (threadIdx.x == 0) {
        float m = red[0];
#pragma unroll
        for (int j = 1; j < 8; j++) m = fmaxf(m, red[j]);
        float sc = __fdiv_rn(fmaxf(m, EPSV), FP8MAX);
        s_scale = sc;
        g_Xs[row] = sc;
    }
    __syncthreads();
    const float sc = s_scale;

    uint32_t* oq = (uint32_t*)(g_Xq + (size_t)row * K_DIM);
#pragma unroll
    for (int i = 0; i < 4; i++) {
        float b0 = a0[i], b1 = a1[i], b2 = a2[i], b3 = a3[i];
        int i1 = 0; float m1 = b0;
        if (b1 > m1) { m1 = b1; i1 = 1; }
        if (b2 > m1) { m1 = b2; i1 = 2; }
        if (b3 > m1) { m1 = b3; i1 = 3; }
        float c0 = (i1 == 0) ? -1.f : b0;
        float c1 = (i1 == 1) ? -1.f : b1;
        float c2 = (i1 == 2) ? -1.f : b2;
        float c3 = (i1 == 3) ? -1.f : b3;
        int i2 = 0; float m2 = c0;
        if (c1 > m2) { m2 = c1; i2 = 1; }
        if (c2 > m2) { m2 = c2; i2 = 2; }
        if (c3 > m2) { m2 = c3; i2 = 3; }

        float q0 = (i1 == 0 || i2 == 0) ? __fdiv_rn(b0, sc) : 0.f;
        float q1 = (i1 == 1 || i2 == 1) ? __fdiv_rn(b1, sc) : 0.f;
        float q2 = (i1 == 2 || i2 == 2) ? __fdiv_rn(b2, sc) : 0.f;
        float q3 = (i1 == 3 || i2 == 3) ? __fdiv_rn(b3, sc) : 0.f;

        uint16_t lo = cvt_e4m3x2(q0, q1);
        uint16_t hi = cvt_e4m3x2(q2, q3);
        oq[threadIdx.x + i * 256] = (uint32_t)lo | ((uint32_t)hi << 16);
    }
}

// ----------------------------- dense fp8 GEMM -------------------------------
// 128x256 CTA tile, 8 warps (2x4), warp tile 64x64 (mi=4, ni=8). BK=64 per
// stage (2 x k32 steps), 6-stage cp.async ring, 1 CTA/SM.
// 64B rows, 16B-chunk swizzle: chunk' = chunk ^ ((row>>1)&3).
__global__ void __launch_bounds__(256, 1) gemm_kernel(float* __restrict__ out) {
    extern __shared__ uint32_t sm[];
    const uint32_t sb = smem_u32(sm);
    const int tid = threadIdx.x;
    const int wid = tid >> 5;
    const int lane = tid & 31;
    const int gid = lane >> 2;
    const int t4 = lane & 3;
    const int wm = (wid >> 2) * 64;   // 0 / 64
    const int wn = (wid & 3) * 64;    // 0 / 64 / 128 / 192
    const int m0 = blockIdx.y * BM;
    const int n0 = blockIdx.x * BN;

    // ---- ldmatrix lane address components ----
    const int ar = lane & 15;
    const uint32_t hiA = (uint32_t)lane >> 4;       // +0/+1 chunk within k32
    const uint32_t swzA = ((uint32_t)ar >> 1) & 3;
    const uint32_t aAbase = (uint32_t)(wm + ar) * 64;
    const uint32_t swzB = ((uint32_t)lane >> 1) & 3;
    const uint32_t aBbase0 = B_OFF + (uint32_t)(wn + lane) * 64;        // rows wn+0..31
    const uint32_t aBbase1 = aBbase0 + 32 * 64;                          // rows wn+32..63

    // ---- producer mapping: thread -> A row (2 chunks) + 2 B rows (2 chunks) ----
    const int prow = tid >> 1;          // 0..127
    const int pcb = (tid & 1) * 2;      // chunk base 0/2
    const uint32_t swzP = ((uint32_t)prow >> 1) & 3;
    const uint8_t* pA  = g_Xq + (size_t)(m0 + prow) * K_DIM + pcb * 16;
    const uint8_t* pB0 = g_Wq + (size_t)(n0 + prow) * K_DIM + pcb * 16;
    const uint8_t* pB1 = g_Wq + (size_t)(n0 + prow + 128) * K_DIM + pcb * 16;
    const uint32_t sA  = sb + (uint32_t)prow * 64 + (((uint32_t)pcb ^ swzP) << 4);
    const uint32_t sB0 = sA + B_OFF;
    const uint32_t sB1 = sB0 + 128 * 64;

    float acc[4][8][4];
#pragma unroll
    for (int i = 0; i < 4; i++)
#pragma unroll
        for (int j = 0; j < 8; j++)
#pragma unroll
            for (int c = 0; c < 4; c++) acc[i][j][c] = 0.f;

    // ---- prologue: fill STAGES-1 stages ----
#pragma unroll
    for (int s = 0; s < STAGES - 1; s++) {
        const uint32_t po = s * STG_BYTES;
        const size_t gk = (size_t)s * BK;
        cp16(sA + po, pA + gk);
        cp16((sA + po) ^ 0x10, pA + gk + 16);
        cp16(sB0 + po, pB0 + gk);
        cp16((sB0 + po) ^ 0x10, pB0 + gk + 16);
        cp16(sB1 + po, pB1 + gk);
        cp16((sB1 + po) ^ 0x10, pB1 + gk + 16);
        cp_commit();
    }

    // ---- main loop ----
#pragma unroll 1
    for (int kt = 0; kt < KT; kt++) {
        cp_wait<STAGES - 2>();
        __syncthreads();

        if (kt + STAGES - 1 < KT) {
            const uint32_t po = ((kt + STAGES - 1) % STAGES) * STG_BYTES;
            const size_t gk = (size_t)(kt + STAGES - 1) * BK;
            cp16(sA + po, pA + gk);
            cp16((sA + po) ^ 0x10, pA + gk + 16);
            cp16(sB0 + po, pB0 + gk);
            cp16((sB0 + po) ^ 0x10, pB0 + gk + 16);
            cp16(sB1 + po, pB1 + gk);
            cp16((sB1 + po) ^ 0x10, pB1 + gk + 16);
        }
        cp_commit();

        const uint32_t co = (kt % STAGES) * STG_BYTES;

        // ---- bulk fragment load: 16 ldsm4 ----
        uint32_t af[2][4][4];        // [j][mi][reg]
        uint32_t bb[2][2][2][4];     // [j][rowhalf][chunk][q]
#pragma unroll
        for (int j = 0; j < 2; j++) {
            const uint32_t cA = 2u * j + hiA;
            const uint32_t offA = ((cA ^ swzA) << 4);
#pragma unroll
            for (int mi = 0; mi < 4; mi++)
                ldsm4(af[j][mi], sb + co + aAbase + (uint32_t)mi * 1024 + offA);
            const uint32_t off0 = (((2u * j)     ^ swzB) << 4);
            const uint32_t off1 = (((2u * j + 1) ^ swzB) << 4);
            ldsm4(bb[j][0][0], sb + co + aBbase0 + off0);
            ldsm4(bb[j][0][1], sb + co + aBbase0 + off1);
            ldsm4(bb[j][1][0], sb + co + aBbase1 + off0);
            ldsm4(bb[j][1][1], sb + co + aBbase1 + off1);
        }

        // ---- 64 MMAs ----
#pragma unroll
        for (int j = 0; j < 2; j++)
#pragma unroll
            for (int mi = 0; mi < 4; mi++)
#pragma unroll
                for (int ni = 0; ni < 8; ni++)
                    mma_fp8(acc[mi][ni], af[j][mi],
                            bb[j][ni >> 2][0][ni & 3], bb[j][ni >> 2][1][ni & 3]);
    }

    // ---- epilogue: rescale + store ----
#pragma unroll
    for (int mi = 0; mi < 4; mi++) {
        const int r0 = m0 + wm + mi * 16 + gid;
        const float xs0 = g_Xs[r0];
        const float xs1 = g_Xs[r0 + 8];
#pragma unroll
        for (int ni = 0; ni < 8; ni++) {
            const int c = n0 + wn + ni * 8 + t4 * 2;
            const float ws0 = g_Ws[c];
            const float ws1 = g_Ws[c + 1];
            float2 o0, o1;
            o0.x = acc[mi][ni][0] * xs0 * ws0;
            o0.y = acc[mi][ni][1] * xs0 * ws1;
            o1.x = acc[mi][ni][2] * xs1 * ws0;
            o1.y = acc[mi][ni][3] * xs1 * ws1;
            *(float2*)(out + (size_t)r0 * N_DIM + c) = o0;
            *(float2*)(out + (size_t)(r0 + 8) * N_DIM + c) = o1;
        }
    }
}

// ----------------------------- launch ---------------------------------------
extern "C" void kernel_launch(void* const* d_in, const int* in_sizes, int n_in,
                              void* d_out, int out_size) {
    const float* x = (const float*)d_in[0];   // [8192, 4096] f32
    const float* w = (const float*)d_in[1];   // [4096, 4096] f32
    float* out = (float*)d_out;               // [8192, 4096] f32
    (void)in_sizes; (void)n_in; (void)out_size;

    cudaFuncSetAttribute(gemm_kernel,
                         cudaFuncAttributeMaxDynamicSharedMemorySize, SMEM_BYTES);

    wquant_kernel<<<N_DIM, 256>>>(w);
    aquant_kernel<<<M_DIM, 256>>>(x);
    gemm_kernel<<<dim3(N_DIM / BN, M_DIM / BM), 256, SMEM_BYTES>>>(out);
}

// round 7
// speedup vs baseline: 1.2755x; 1.0181x over previous
#include <cuda_runtime.h>
#include <cstdint>

// ----------------------------- problem constants -----------------------------
#define M_DIM 8192
#define N_DIM 4096
#define K_DIM 4096
#define FP8MAX 448.0f
#define EPSV 1e-12f

// ----------------------------- GEMM tiling ----------------------------------
#define BM 128
#define BN 128
#define BK 64                   // K fp8 elems per stage (4 x k16 HMMA steps)
#define STAGES 6
#define KT (K_DIM / BK)         // 64 k-tiles

// per-stage smem: A[128][64B] + B[128][64B] = 16 KB
#define STG_BYTES 16384
#define B_OFF 8192
#define SMEM_BYTES (STAGES * STG_BYTES)   // 98304

// ----------------------------- scratch (static device mem) ------------------
// fp8 codes stored k-PERMUTED: within each 16-elem window,
// stored[4t+0,4t+1,4t+2,4t+3] = orig[2t, 2t+1, 2t+8, 2t+9]  (t = 0..3)
__device__ __align__(256) uint8_t g_Xq[(size_t)M_DIM * K_DIM];
__device__ __align__(256) uint8_t g_Wq[(size_t)N_DIM * K_DIM];
__device__ __align__(16) float g_Xs[M_DIM];
__device__ __align__(16) float g_Ws[N_DIM];

// ----------------------------- PTX helpers ----------------------------------
__device__ __forceinline__ uint32_t smem_u32(const void* p) {
    uint32_t a;
    asm("{ .reg .u64 t; cvta.to.shared.u64 t, %1; cvt.u32.u64 %0, t; }"
        : "=r"(a) : "l"(p));
    return a;
}
__device__ __forceinline__ void cp16(uint32_t s, const void* g) {
    asm volatile("cp.async.cg.shared.global [%0], [%1], 16;" :: "r"(s), "l"(g));
}
__device__ __forceinline__ void cp_commit() {
    asm volatile("cp.async.commit_group;" ::: "memory");
}
template <int N>
__device__ __forceinline__ void cp_wait() {
    asm volatile("cp.async.wait_group %0;" :: "n"(N) : "memory");
}
__device__ __forceinline__ void ldsm4(uint32_t* r, uint32_t addr) {
    asm volatile("ldmatrix.sync.aligned.m8n8.x4.shared.b16 {%0,%1,%2,%3}, [%4];"
                 : "=r"(r[0]), "=r"(r[1]), "=r"(r[2]), "=r"(r[3]) : "r"(addr));
}
// split 4 packed e4m3 -> two f16x2 regs (lo = fp8 bytes 0,1; hi = bytes 2,3)
__device__ __forceinline__ void cvt8x4(uint32_t r, uint32_t& lo, uint32_t& hi) {
    asm("{ .reg .b16 l, h;\n\t"
        "mov.b32 {l, h}, %2;\n\t"
        "cvt.rn.f16x2.e4m3x2 %0, l;\n\t"
        "cvt.rn.f16x2.e4m3x2 %1, h; }"
        : "=r"(lo), "=r"(hi) : "r"(r));
}
__device__ __forceinline__ void mma_f16(float* d, uint32_t a0, uint32_t a1,
                                        uint32_t a2, uint32_t a3,
                                        uint32_t b0, uint32_t b1) {
    asm volatile(
        "mma.sync.aligned.m16n8k16.row.col.f32.f16.f16.f32 "
        "{%0,%1,%2,%3}, {%4,%5,%6,%7}, {%8,%9}, {%0,%1,%2,%3};"
        : "+f"(d[0]), "+f"(d[1]), "+f"(d[2]), "+f"(d[3])
        : "r"(a0), "r"(a1), "r"(a2), "r"(a3), "r"(b0), "r"(b1));
}
// pack two f32 -> e4m3x2 (lo in low byte), RN + satfinite
__device__ __forceinline__ uint16_t cvt_e4m3x2(float lo, float hi) {
    uint16_t r;
    asm volatile("cvt.rn.satfinite.e4m3x2.f32 %0, %1, %2;" : "=h"(r) : "f"(hi), "f"(lo));
    return r;
}

// ----------------------------- weight quant (k-permuted output) -------------
// one CTA per row, one 16-elem k-window per thread.
__global__ void __launch_bounds__(256) wquant_kernel(const float* __restrict__ w) {
    const int row = blockIdx.x;
    const int t = threadIdx.x;
    const float4* wr = (const float4*)(w + (size_t)row * K_DIM);

    float4 v[4];
    float mx = 0.f;
#pragma unroll
    for (int i = 0; i < 4; i++) {
        v[i] = wr[4 * t + i];
        mx = fmaxf(mx, fmaxf(fmaxf(fabsf(v[i].x), fabsf(v[i].y)),
                             fmaxf(fabsf(v[i].z), fabsf(v[i].w))));
    }
    __shared__ float red[8];
    __shared__ float s_scale;
#pragma unroll
    for (int o = 16; o; o >>= 1) mx = fmaxf(mx, __shfl_xor_sync(0xffffffffu, mx, o));
    if ((t & 31) == 0) red[t >> 5] = mx;
    __syncthreads();
    if (t == 0) {
        float m = red[0];
#pragma unroll
        for (int j = 1; j < 8; j++) m = fmaxf(m, red[j]);
        float sc = __fdiv_rn(fmaxf(m, EPSV), FP8MAX);
        s_scale = sc;
        g_Ws[row] = sc;
    }
    __syncthreads();
    const float sc = s_scale;

    // q[o] for o = 0..15 (orig order)
    float q[16];
#pragma unroll
    for (int i = 0; i < 4; i++) {
        q[4 * i + 0] = __fdiv_rn(v[i].x, sc);
        q[4 * i + 1] = __fdiv_rn(v[i].y, sc);
        q[4 * i + 2] = __fdiv_rn(v[i].z, sc);
        q[4 * i + 3] = __fdiv_rn(v[i].w, sc);
    }
    uint32_t ph[8];
#pragma unroll
    for (int p = 0; p < 8; p++) ph[p] = cvt_e4m3x2(q[2 * p], q[2 * p + 1]);
    uint4 o;
    o.x = ph[0] | (ph[4] << 16);
    o.y = ph[1] | (ph[5] << 16);
    o.z = ph[2] | (ph[6] << 16);
    o.w = ph[3] | (ph[7] << 16);
    ((uint4*)(g_Wq + (size_t)row * K_DIM))[t] = o;
}

// ----------------------------- activation quant (srelu + 2:4, permuted) -----
__global__ void __launch_bounds__(256) aquant_kernel(const float* __restrict__ x) {
    const int row = blockIdx.x;
    const int t = threadIdx.x;
    const float4* xr = (const float4*)(x + (size_t)row * K_DIM);

    float b[16];
    float mx = 0.f;
#pragma unroll
    for (int i = 0; i < 4; i++) {
        float4 v = xr[4 * t + i];
        float r0 = fmaxf(v.x, 0.f), r1 = fmaxf(v.y, 0.f);
        float r2 = fmaxf(v.z, 0.f), r3 = fmaxf(v.w, 0.f);
        b[4 * i + 0] = r0 * r0; b[4 * i + 1] = r1 * r1;
        b[4 * i + 2] = r2 * r2; b[4 * i + 3] = r3 * r3;
        mx = fmaxf(mx, fmaxf(fmaxf(b[4 * i], b[4 * i + 1]),
                             fmaxf(b[4 * i + 2], b[4 * i + 3])));
    }
    __shared__ float red[8];
    __shared__ float s_scale;
#pragma unroll
    for (int o = 16; o; o >>= 1) mx = fmaxf(mx, __shfl_xor_sync(0xffffffffu, mx, o));
    if ((t & 31) == 0) red[t >> 5] = mx;
    __syncthreads();
    if (t == 0) {
        float m = red[0];
#pragma unroll
        for (int j = 1; j < 8; j++) m = fmaxf(m, red[j]);
        float sc = __fdiv_rn(fmaxf(m, EPSV), FP8MAX);
        s_scale = sc;
        g_Xs[row] = sc;
    }
    __syncthreads();
    const float sc = s_scale;

    float q[16];
#pragma unroll
    for (int i = 0; i < 4; i++) {
        float b0 = b[4 * i], b1 = b[4 * i + 1], b2 = b[4 * i + 2], b3 = b[4 * i + 3];
        int i1 = 0; float m1 = b0;
        if (b1 > m1) { m1 = b1; i1 = 1; }
        if (b2 > m1) { m1 = b2; i1 = 2; }
        if (b3 > m1) { m1 = b3; i1 = 3; }
        float c0 = (i1 == 0) ? -1.f : b0;
        float c1 = (i1 == 1) ? -1.f : b1;
        float c2 = (i1 == 2) ? -1.f : b2;
        float c3 = (i1 == 3) ? -1.f : b3;
        int i2 = 0; float m2 = c0;
        if (c1 > m2) { m2 = c1; i2 = 1; }
        if (c2 > m2) { m2 = c2; i2 = 2; }
        if (c3 > m2) { m2 = c3; i2 = 3; }
        q[4 * i + 0] = (i1 == 0 || i2 == 0) ? __fdiv_rn(b0, sc) : 0.f;
        q[4 * i + 1] = (i1 == 1 || i2 == 1) ? __fdiv_rn(b1, sc) : 0.f;
        q[4 * i + 2] = (i1 == 2 || i2 == 2) ? __fdiv_rn(b2, sc) : 0.f;
        q[4 * i + 3] = (i1 == 3 || i2 == 3) ? __fdiv_rn(b3, sc) : 0.f;
    }
    uint32_t ph[8];
#pragma unroll
    for (int p = 0; p < 8; p++) ph[p] = cvt_e4m3x2(q[2 * p], q[2 * p + 1]);
    uint4 o;
    o.x = ph[0] | (ph[4] << 16);
    o.y = ph[1] | (ph[5] << 16);
    o.z = ph[2] | (ph[6] << 16);
    o.w = ph[3] | (ph[7] << 16);
    ((uint4*)(g_Xq + (size_t)row * K_DIM))[t] = o;
}

// ----------------------------- fp16 HMMA GEMM on fp8 codes ------------------
// 128x128 CTA tile, 16 warps (4x4), warp tile 32x32. BK=64 per stage
// (4 x k16 HMMA steps), 6-stage cp.async ring, 512 threads, 1 CTA/SM.
// 64B rows, 16B-chunk swizzle: chunk' = chunk ^ ((row>>1)&3).
__global__ void __launch_bounds__(512, 1) gemm_kernel(float* __restrict__ out) {
    extern __shared__ uint32_t sm[];
    const uint32_t sb = smem_u32(sm);
    const int tid = threadIdx.x;
    const int wid = tid >> 5;
    const int lane = tid & 31;
    const int gid = lane >> 2;
    const int t4 = lane & 3;
    const int wm = (wid >> 2) * 32;   // 0/32/64/96
    const int wn = (wid & 3) * 32;    // 0/32/64/96
    const int m0 = blockIdx.y * BM;
    const int n0 = blockIdx.x * BN;

    // ---- ldmatrix lane address components ----
    const int ar = lane & 15;
    const uint32_t hiA = (uint32_t)lane >> 4;          // chunk +0/+1
    const uint32_t swzA = ((uint32_t)ar >> 1) & 3;
    const uint32_t aAbase = (uint32_t)(wm + ar) * 64;
    const uint32_t swzB = ((uint32_t)lane >> 1) & 3;
    const uint32_t aBbase = B_OFF + (uint32_t)(wn + lane) * 64;

    // ---- producer mapping: 512 threads -> 256 rows x 2 chunks ----
    const int prow = tid >> 1;          // 0..255 (A: 0-127, B: 128-255)
    const int pcb = (tid & 1) * 2;      // chunk base 0/2
    const uint8_t* gP = (prow < 128)
        ? g_Xq + (size_t)(m0 + prow) * K_DIM + pcb * 16
        : g_Wq + (size_t)(n0 + (prow - 128)) * K_DIM + pcb * 16;
    const uint32_t swzP = ((uint32_t)prow >> 1) & 3;   // (row&127)>>1 same low bits
    const uint32_t sP = sb + (uint32_t)prow * 64 + (((uint32_t)pcb ^ swzP) << 4);

    float acc[2][4][4];
#pragma unroll
    for (int i = 0; i < 2; i++)
#pragma unroll
        for (int j = 0; j < 4; j++)
#pragma unroll
            for (int c = 0; c < 4; c++) acc[i][j][c] = 0.f;

    // ---- prologue: fill STAGES-1 stages ----
#pragma unroll
    for (int s = 0; s < STAGES - 1; s++) {
        const uint32_t po = s * STG_BYTES;
        const size_t gk = (size_t)s * BK;
        cp16(sP + po, gP + gk);
        cp16((sP + po) ^ 0x10, gP + gk + 16);
        cp_commit();
    }

    // ---- main loop ----
#pragma unroll 1
    for (int kt = 0; kt < KT; kt++) {
        cp_wait<STAGES - 2>();
        __syncthreads();

        if (kt + STAGES - 1 < KT) {
            const uint32_t po = ((kt + STAGES - 1) % STAGES) * STG_BYTES;
            const size_t gk = (size_t)(kt + STAGES - 1) * BK;
            cp16(sP + po, gP + gk);
            cp16((sP + po) ^ 0x10, gP + gk + 16);
        }
        cp_commit();

        const uint32_t co = (kt % STAGES) * STG_BYTES;

        // ---- bulk ldsm: 8 x ldsm4 = 32 fp8 regs ----
        // A: afp[mi][cpair][r]: r0 = rows0-7 chunk 2*cpair+hiA, r1 = rows8-15,
        //                       r2/r3 = chunk +1 pattern via hiA lanes
        uint32_t afp[2][2][4];
#pragma unroll
        for (int mi = 0; mi < 2; mi++)
#pragma unroll
            for (int cp = 0; cp < 2; cp++) {
                const uint32_t c = 2u * cp + hiA;
                ldsm4(afp[mi][cp],
                      sb + co + aAbase + (uint32_t)mi * 1024 + (((c) ^ swzA) << 4));
            }
        // B: bfp[c][ni]
        uint32_t bfp[4][4];
#pragma unroll
        for (int c = 0; c < 4; c++)
            ldsm4(bfp[c], sb + co + aBbase + ((((uint32_t)c) ^ swzB) << 4));

        // ---- per k16 chunk: cvt fp8->f16, then 8 HMMAs ----
#pragma unroll
        for (int c = 0; c < 4; c++) {
            const int cp = c >> 1, cl = (c & 1) * 2;
            uint32_t a0[2], a1[2], a2[2], a3[2];
#pragma unroll
            for (int mi = 0; mi < 2; mi++) {
                cvt8x4(afp[mi][cp][cl + 0], a0[mi], a2[mi]);   // rows gid
                cvt8x4(afp[mi][cp][cl + 1], a1[mi], a3[mi]);   // rows gid+8
            }
            uint32_t b0[4], b1[4];
#pragma unroll
            for (int ni = 0; ni < 4; ni++)
                cvt8x4(bfp[c][ni], b0[ni], b1[ni]);
#pragma unroll
            for (int mi = 0; mi < 2; mi++)
#pragma unroll
                for (int ni = 0; ni < 4; ni++)
                    mma_f16(acc[mi][ni], a0[mi], a1[mi], a2[mi], a3[mi],
                            b0[ni], b1[ni]);
        }
    }

    // ---- epilogue: rescale + store ----
#pragma unroll
    for (int mi = 0; mi < 2; mi++) {
        const int r0 = m0 + wm + mi * 16 + gid;
        const float xs0 = g_Xs[r0];
        const float xs1 = g_Xs[r0 + 8];
#pragma unroll
        for (int ni = 0; ni < 4; ni++) {
            const int c = n0 + wn + ni * 8 + t4 * 2;
            const float ws0 = g_Ws[c];
            const float ws1 = g_Ws[c + 1];
            float2 o0, o1;
            o0.x = acc[mi][ni][0] * xs0 * ws0;
            o0.y = acc[mi][ni][1] * xs0 * ws1;
            o1.x = acc[mi][ni][2] * xs1 * ws0;
            o1.y = acc[mi][ni][3] * xs1 * ws1;
            *(float2*)(out + (size_t)r0 * N_DIM + c) = o0;
            *(float2*)(out + (size_t)(r0 + 8) * N_DIM + c) = o1;
        }
    }
}

// ----------------------------- launch ---------------------------------------
extern "C" void kernel_launch(void* const* d_in, const int* in_sizes, int n_in,
                              void* d_out, int out_size) {
    const float* x = (const float*)d_in[0];   // [8192, 4096] f32
    const float* w = (const float*)d_in[1];   // [4096, 4096] f32
    float* out = (float*)d_out;               // [8192, 4096] f32
    (void)in_sizes; (void)n_in; (void)out_size;

    cudaFuncSetAttribute(gemm_kernel,
                         cudaFuncAttributeMaxDynamicSharedMemorySize, SMEM_BYTES);

    wquant_kernel<<<N_DIM, 256>>>(w);
    aquant_kernel<<<M_DIM, 256>>>(x);
    gemm_kernel<<<dim3(N_DIM / BN, M_DIM / BM), 512, SMEM_BYTES>>>(out);
}